// round 14
// baseline (speedup 1.0000x reference)
#include <cuda_runtime.h>
#include <cuda_bf16.h>
#include <cstdint>
#include <cstddef>

#define SEQ 4096
#define DM  1024
#define NH  16
#define DH  64

// Scratch: Q/K/V stored as bf16 hi/lo split, head-major [h][s][d]
__device__ __align__(16) __nv_bfloat16 g_Qbh[NH * SEQ * DH];
__device__ __align__(16) __nv_bfloat16 g_Qbl[NH * SEQ * DH];
__device__ __align__(16) __nv_bfloat16 g_Kbh[NH * SEQ * DH];
__device__ __align__(16) __nv_bfloat16 g_Kbl[NH * SEQ * DH];
__device__ __align__(16) __nv_bfloat16 g_Vbh[NH * SEQ * DH];
__device__ __align__(16) __nv_bfloat16 g_Vbl[NH * SEQ * DH];
__device__ float g_vals[SEQ * DM];      // [s][h*64+d]
__device__ float g_invl[NH * SEQ];      // per-row 1/sumexp

// ---------------------------------------------------------------------------
// Helpers
// ---------------------------------------------------------------------------
__device__ __forceinline__ uint32_t s2u(const void* p) {
    return (uint32_t)__cvta_generic_to_shared(p);
}

__device__ __forceinline__ void ldsm_x4(uint32_t* r, uint32_t a) {
    asm volatile("ldmatrix.sync.aligned.m8n8.x4.shared.b16 {%0,%1,%2,%3}, [%4];"
                 : "=r"(r[0]), "=r"(r[1]), "=r"(r[2]), "=r"(r[3]) : "r"(a));
}

__device__ __forceinline__ void ldsm_x4t(uint32_t* r, uint32_t a) {
    asm volatile("ldmatrix.sync.aligned.m8n8.x4.trans.shared.b16 {%0,%1,%2,%3}, [%4];"
                 : "=r"(r[0]), "=r"(r[1]), "=r"(r[2]), "=r"(r[3]) : "r"(a));
}

__device__ __forceinline__ void mma_bf16(float* c, const uint32_t* a, uint32_t b0, uint32_t b1) {
    asm volatile("mma.sync.aligned.m16n8k16.row.col.f32.bf16.bf16.f32 "
                 "{%0,%1,%2,%3}, {%4,%5,%6,%7}, {%8,%9}, {%0,%1,%2,%3};"
                 : "+f"(c[0]), "+f"(c[1]), "+f"(c[2]), "+f"(c[3])
                 : "r"(a[0]), "r"(a[1]), "r"(a[2]), "r"(a[3]), "r"(b0), "r"(b1));
}

__device__ __forceinline__ uint32_t pack2(float a, float b) {
    __nv_bfloat162 t = __floats2bfloat162_rn(a, b);
    return *(uint32_t*)&t;
}

// ---------------------------------------------------------------------------
// GEMM core v2: 128x64 block tile, 256 threads (8 warps: 4m x 2n), K=32 chunks.
// X smem stride 40 elem (80B, conflict-free), W smem stride 72 (144B).
// Static smem 29 KB; 2 CTAs/SM via launch_bounds; staging = 24 regs.
// ---------------------------------------------------------------------------
#define XS 40
#define WS 72

__device__ __forceinline__ void g2_load_regs(float4* xr, float4* wr,
                                             const float* __restrict__ Xp,
                                             const float* __restrict__ Wp,
                                             int k0, int tid) {
    #pragma unroll
    for (int it = 0; it < 4; it++) {            // X: 128 rows x 32 k
        int lin = tid + it * 256;
        int row = lin >> 3;
        int c4  = (lin & 7) * 4;
        xr[it] = *(const float4*)(Xp + (size_t)row * DM + k0 + c4);
    }
    #pragma unroll
    for (int it = 0; it < 2; it++) {            // W: 32 k x 64 n
        int lin = tid + it * 256;
        int row = lin >> 4;
        int c4  = (lin & 15) * 4;
        wr[it] = *(const float4*)(Wp + (size_t)(k0 + row) * DM + c4);
    }
}

__device__ __forceinline__ void g2_cvt4(float4 v, __nv_bfloat16* Bh, __nv_bfloat16* Bl,
                                        int off) {
    __nv_bfloat16 h0 = __float2bfloat16_rn(v.x);
    __nv_bfloat16 h1 = __float2bfloat16_rn(v.y);
    __nv_bfloat16 h2 = __float2bfloat16_rn(v.z);
    __nv_bfloat16 h3 = __float2bfloat16_rn(v.w);
    *(__nv_bfloat162*)(Bh + off)     = __halves2bfloat162(h0, h1);
    *(__nv_bfloat162*)(Bh + off + 2) = __halves2bfloat162(h2, h3);
    *(__nv_bfloat162*)(Bl + off) =
        __floats2bfloat162_rn(v.x - __bfloat162float(h0), v.y - __bfloat162float(h1));
    *(__nv_bfloat162*)(Bl + off + 2) =
        __floats2bfloat162_rn(v.z - __bfloat162float(h2), v.w - __bfloat162float(h3));
}

__device__ __forceinline__ void gemm_core2(const float* __restrict__ X,
                                           const float* __restrict__ W,
                                           const float* __restrict__ bias,
                                           float* __restrict__ dstf,
                                           __nv_bfloat16* __restrict__ dsth,
                                           __nv_bfloat16* __restrict__ dstl,
                                           float scale, int m0, int n0) {
    __shared__ __nv_bfloat16 Xsh[128 * XS];
    __shared__ __nv_bfloat16 Xsl[128 * XS];
    __shared__ __nv_bfloat16 Wsh[32 * WS];
    __shared__ __nv_bfloat16 Wsl[32 * WS];

    const int tid  = threadIdx.x;
    const int lane = tid & 31;
    const int w    = tid >> 5;
    const int wm   = w & 3;        // M quarter (32 rows)
    const int wn   = w >> 2;       // N half (32 cols)
    const int grp  = lane >> 3;
    const int li   = lane & 7;

    const float* Xp = X + (size_t)m0 * DM;
    const float* Wp = W + n0;

    float vacc[8][4];
    #pragma unroll
    for (int t = 0; t < 8; t++) {
        #pragma unroll
        for (int j = 0; j < 4; j++) vacc[t][j] = 0.f;
    }

    float4 xr[4], wr[2];
    g2_load_regs(xr, wr, Xp, Wp, 0, tid);

    for (int k0 = 0; k0 < DM; k0 += 32) {
        #pragma unroll
        for (int it = 0; it < 4; it++) {
            int lin = tid + it * 256;
            int row = lin >> 3;
            int c4  = (lin & 7) * 4;
            g2_cvt4(xr[it], Xsh, Xsl, row * XS + c4);
        }
        #pragma unroll
        for (int it = 0; it < 2; it++) {
            int lin = tid + it * 256;
            int row = lin >> 4;
            int c4  = (lin & 15) * 4;
            g2_cvt4(wr[it], Wsh, Wsl, row * WS + c4);
        }
        __syncthreads();

        if (k0 + 32 < DM)
            g2_load_regs(xr, wr, Xp, Wp, k0 + 32, tid);  // hidden under MMA

        #pragma unroll
        for (int kg = 0; kg < 2; kg++) {
            uint32_t ah[2][4], al[2][4];
            #pragma unroll
            for (int mh = 0; mh < 2; mh++) {
                int arow = wm * 32 + mh * 16 + (grp & 1) * 8 + li;
                int acol = kg * 16 + (grp >> 1) * 8;
                ldsm_x4(ah[mh], s2u(Xsh + arow * XS + acol));
                ldsm_x4(al[mh], s2u(Xsl + arow * XS + acol));
            }
            #pragma unroll
            for (int t = 0; t < 2; t++) {
                int vrow = kg * 16 + (grp & 1) * 8 + li;
                int vcol = wn * 32 + t * 16 + (grp >> 1) * 8;
                uint32_t vh[4], vl[4];
                ldsm_x4t(vh, s2u(Wsh + vrow * WS + vcol));
                ldsm_x4t(vl, s2u(Wsl + vrow * WS + vcol));
                #pragma unroll
                for (int mh = 0; mh < 2; mh++) {
                    float* c0p = vacc[mh * 4 + t * 2];
                    float* c1p = vacc[mh * 4 + t * 2 + 1];
                    mma_bf16(c0p, ah[mh], vh[0], vh[1]);
                    mma_bf16(c0p, al[mh], vh[0], vh[1]);
                    mma_bf16(c0p, ah[mh], vl[0], vl[1]);
                    mma_bf16(c1p, ah[mh], vh[2], vh[3]);
                    mma_bf16(c1p, al[mh], vh[2], vh[3]);
                    mma_bf16(c1p, ah[mh], vl[2], vl[3]);
                }
            }
        }
        __syncthreads();
    }

    const int r0 = lane >> 2;
    const int c0 = (lane & 3) * 2;
    #pragma unroll
    for (int u = 0; u < 8; u++) {
        int mh = u >> 2, q = u & 3;
        int row0 = m0 + wm * 32 + mh * 16 + r0;
        int coff = wn * 32 + q * 8 + c0;
        int col  = n0 + coff;
        float b0 = bias[col], b1 = bias[col + 1];
        float v00 = (vacc[u][0] + b0) * scale;
        float v01 = (vacc[u][1] + b1) * scale;
        float v10 = (vacc[u][2] + b0) * scale;
        float v11 = (vacc[u][3] + b1) * scale;
        if (dsth) {
            int hh = n0 >> 6;
            size_t base0 = ((size_t)hh * SEQ + row0) * DH + coff;
            size_t base1 = ((size_t)hh * SEQ + row0 + 8) * DH + coff;
            __nv_bfloat16 h00 = __float2bfloat16_rn(v00);
            __nv_bfloat16 h01 = __float2bfloat16_rn(v01);
            __nv_bfloat16 h10 = __float2bfloat16_rn(v10);
            __nv_bfloat16 h11 = __float2bfloat16_rn(v11);
            *(__nv_bfloat162*)&dsth[base0] = __halves2bfloat162(h00, h01);
            *(__nv_bfloat162*)&dsth[base1] = __halves2bfloat162(h10, h11);
            *(__nv_bfloat162*)&dstl[base0] =
                __floats2bfloat162_rn(v00 - __bfloat162float(h00), v01 - __bfloat162float(h01));
            *(__nv_bfloat162*)&dstl[base1] =
                __floats2bfloat162_rn(v10 - __bfloat162float(h10), v11 - __bfloat162float(h11));
        } else {
            *(float2*)&dstf[(size_t)row0 * DM + col]       = make_float2(v00, v01);
            *(float2*)&dstf[(size_t)(row0 + 8) * DM + col] = make_float2(v10, v11);
        }
    }
}

__global__ __launch_bounds__(256, 2) void proj_kernel(
    const float* __restrict__ xq, const float* __restrict__ xk, const float* __restrict__ xv,
    const float* __restrict__ Wq, const float* __restrict__ bq,
    const float* __restrict__ Wk, const float* __restrict__ bk,
    const float* __restrict__ Wv, const float* __restrict__ bv)
{
    const float* X; const float* W; const float* b;
    __nv_bfloat16 *dh, *dl; float scale;
    // Q scale folds softmax 1/8 AND log2(e) so attn can use exp2f directly.
    if (blockIdx.z == 0)      { X = xq; W = Wq; b = bq; dh = g_Qbh; dl = g_Qbl; scale = 0.125f * 1.4426950408889634f; }
    else if (blockIdx.z == 1) { X = xk; W = Wk; b = bk; dh = g_Kbh; dl = g_Kbl; scale = 1.0f; }
    else                      { X = xv; W = Wv; b = bv; dh = g_Vbh; dl = g_Vbl; scale = 1.0f; }
    gemm_core2(X, W, b, nullptr, dh, dl, scale, blockIdx.y * 128, blockIdx.x * 64);
}

__global__ __launch_bounds__(256, 2) void out_kernel(
    float* __restrict__ out, const float* __restrict__ W, const float* __restrict__ b)
{
    gemm_core2(g_vals, W, b, out, nullptr, nullptr, 1.0f, blockIdx.y * 128, blockIdx.x * 64);
}

// ---------------------------------------------------------------------------
// Attention: 64-query tiles, 128 threads, 2 buffer-pairs, register-staged
// prefetch, 2 syncs/chunk, k-half software pipelining (score/exp interleave).
// ---------------------------------------------------------------------------
// Score MMA over half the keys: C4[4][4] += Q(16x64) @ K^T rows [h0*32, +32)
__device__ __forceinline__ void score_mma_half(float C4[4][4],
                                               const uint32_t qh[4][4], const uint32_t ql[4][4],
                                               const __nv_bfloat16* Bh, const __nv_bfloat16* Bl,
                                               int lane, int h0) {
    const int grp = lane >> 3;
    const int i   = lane & 7;
    #pragma unroll
    for (int t2 = 0; t2 < 2; t2++) {
        int nrow = (h0 * 2 + t2) * 16 + (grp >> 1) * 8 + i;
        int ncol = (grp & 1) * 8;
        #pragma unroll
        for (int g = 0; g < 4; g++) {
            uint32_t kh[4], kl[4];
            ldsm_x4(kh, s2u(Bh + nrow * 72 + g * 16 + ncol));
            ldsm_x4(kl, s2u(Bl + nrow * 72 + g * 16 + ncol));
            mma_bf16(C4[2 * t2],     qh[g], kh[0], kh[1]);
            mma_bf16(C4[2 * t2],     ql[g], kh[0], kh[1]);
            mma_bf16(C4[2 * t2],     qh[g], kl[0], kl[1]);
            mma_bf16(C4[2 * t2 + 1], qh[g], kh[2], kh[3]);
            mma_bf16(C4[2 * t2 + 1], ql[g], kh[2], kh[3]);
            mma_bf16(C4[2 * t2 + 1], qh[g], kl[2], kl[3]);
        }
    }
}

// PV over half the k rows: vacc += P(16 x 32 @ half h0) @ V(rows h0*32..+32)
__device__ __forceinline__ void pv_mma_half(float V[8][4],
                                            const uint32_t pah[4][4], const uint32_t pal[4][4],
                                            const __nv_bfloat16* Bh, const __nv_bfloat16* Bl,
                                            int lane, int h0) {
    const int grp = lane >> 3;
    const int i   = lane & 7;
    #pragma unroll
    for (int t2 = 0; t2 < 4; t2++) {
        int vcol = t2 * 16 + (grp >> 1) * 8;
        #pragma unroll
        for (int gg = 0; gg < 2; gg++) {
            int g = h0 * 2 + gg;
            int vrow = g * 16 + (grp & 1) * 8 + i;
            uint32_t vh[4], vl[4];
            ldsm_x4t(vh, s2u(Bh + vrow * 72 + vcol));
            ldsm_x4t(vl, s2u(Bl + vrow * 72 + vcol));
            mma_bf16(V[2 * t2],     pah[g], vh[0], vh[1]);
            mma_bf16(V[2 * t2],     pal[g], vh[0], vh[1]);
            mma_bf16(V[2 * t2],     pah[g], vl[0], vl[1]);
            mma_bf16(V[2 * t2 + 1], pah[g], vh[2], vh[3]);
            mma_bf16(V[2 * t2 + 1], pal[g], vh[2], vh[3]);
            mma_bf16(V[2 * t2 + 1], pah[g], vl[2], vl[3]);
        }
    }
}

__device__ __forceinline__ void load_pair_regs(uint4* r,
                                               const __nv_bfloat16* __restrict__ Ph,
                                               const __nv_bfloat16* __restrict__ Pl,
                                               int kc, int tid) {
    #pragma unroll
    for (int it = 0; it < 4; it++) {
        int lin = tid + it * 128;
        int row = lin >> 3;
        int c8  = (lin & 7) * 8;
        r[it]     = *(const uint4*)(Ph + (size_t)(kc + row) * DH + c8);
        r[4 + it] = *(const uint4*)(Pl + (size_t)(kc + row) * DH + c8);
    }
}

__device__ __forceinline__ void store_pair_smem(const uint4* r,
                                                __nv_bfloat16* Bh, __nv_bfloat16* Bl,
                                                int tid) {
    #pragma unroll
    for (int it = 0; it < 4; it++) {
        int lin = tid + it * 128;
        int row = lin >> 3;
        int c8  = (lin & 7) * 8;
        *(uint4*)(Bh + row * 72 + c8) = r[it];
        *(uint4*)(Bl + row * 72 + c8) = r[4 + it];
    }
}

__global__ __launch_bounds__(128) void attn_kernel(float* __restrict__ attn_out)
{
    __shared__ __nv_bfloat16 Ash[64 * 72];   // Q staging, then K buffer
    __shared__ __nv_bfloat16 Asl[64 * 72];
    __shared__ __nv_bfloat16 Bsh[64 * 72];   // V buffer
    __shared__ __nv_bfloat16 Bsl[64 * 72];

    const int h    = blockIdx.y;
    const int q0   = blockIdx.x * 64;
    const int tid  = threadIdx.x;
    const int lane = tid & 31;
    const int w    = tid >> 5;

    const __nv_bfloat16* Qh = g_Qbh + ((size_t)h * SEQ + q0) * DH;
    const __nv_bfloat16* Ql = g_Qbl + ((size_t)h * SEQ + q0) * DH;
    const __nv_bfloat16* Kh = g_Kbh + (size_t)h * SEQ * DH;
    const __nv_bfloat16* Kl = g_Kbl + (size_t)h * SEQ * DH;
    const __nv_bfloat16* Vh = g_Vbh + (size_t)h * SEQ * DH;
    const __nv_bfloat16* Vl = g_Vbl + (size_t)h * SEQ * DH;

    // Q -> A buffers
    #pragma unroll
    for (int it = 0; it < 4; it++) {
        int lin = tid + it * 128;
        int row = lin >> 3;
        int c8  = (lin & 7) * 8;
        *(uint4*)&Ash[row * 72 + c8] = *(const uint4*)&Qh[(size_t)row * DH + c8];
        *(uint4*)&Asl[row * 72 + c8] = *(const uint4*)&Ql[(size_t)row * DH + c8];
    }

    uint4 kreg[8], vreg[8];
    load_pair_regs(kreg, Kh, Kl, 0, tid);

    __syncthreads();

    // Q fragments (resident all kernel)
    uint32_t qfh[4][4], qfl[4][4];
    {
        int grp = lane >> 3, i = lane & 7;
        int qrow = w * 16 + (grp & 1) * 8 + i;
        #pragma unroll
        for (int g = 0; g < 4; g++) {
            int qcol = g * 16 + (grp >> 1) * 8;
            ldsm_x4(qfh[g], s2u(Ash + qrow * 72 + qcol));
            ldsm_x4(qfl[g], s2u(Asl + qrow * 72 + qcol));
        }
    }
    __syncthreads();

    store_pair_smem(kreg, Ash, Asl, tid);   // K0 -> A
    __syncthreads();

    float vacc[8][4];
    #pragma unroll
    for (int t = 0; t < 8; t++) {
        #pragma unroll
        for (int j = 0; j < 4; j++) vacc[t][j] = 0.f;
    }
    float lsum0 = 0.f, lsum1 = 0.f;

    const int r0 = lane >> 2;
    const int c0 = (lane & 3) * 2;
    float* arow0 = attn_out + ((size_t)h * SEQ + q0 + w * 16 + r0) * SEQ;
    float* arow1 = arow0 + (size_t)8 * SEQ;

    for (int kc = 0; kc < SEQ; kc += 64) {
        load_pair_regs(vreg, Vh, Vl, kc, tid);

        uint32_t pah[4][4], pal[4][4];

        // ---- two 32-key halves: score -> exp/pack, interleavable ----
        #pragma unroll
        for (int hf = 0; hf < 2; hf++) {
            float C4[4][4];
            #pragma unroll
            for (int t = 0; t < 4; t++) {
                #pragma unroll
                for (int j = 0; j < 4; j++) C4[t][j] = 0.f;
            }
            score_mma_half(C4, qfh, qfl, Ash, Asl, lane, hf);

            if (hf == 0)
                store_pair_smem(vreg, Bsh, Bsl, tid);   // V(kc) -> B (prev PV fenced)

            #pragma unroll
            for (int t = 0; t < 4; t++) {
                float p0 = exp2f(C4[t][0]);
                float p1 = exp2f(C4[t][1]);
                float p2 = exp2f(C4[t][2]);
                float p3 = exp2f(C4[t][3]);
                *(float2*)(arow0 + kc + hf * 32 + t * 8 + c0) = make_float2(p0, p1);
                *(float2*)(arow1 + kc + hf * 32 + t * 8 + c0) = make_float2(p2, p3);
                lsum0 += p0 + p1;
                lsum1 += p2 + p3;
                C4[t][0] = p0; C4[t][1] = p1; C4[t][2] = p2; C4[t][3] = p3;
            }
            #pragma unroll
            for (int gg = 0; gg < 2; gg++) {
                int g = hf * 2 + gg;
                float h00 = __bfloat162float(__float2bfloat16_rn(C4[2*gg][0]));
                float h01 = __bfloat162float(__float2bfloat16_rn(C4[2*gg][1]));
                float h02 = __bfloat162float(__float2bfloat16_rn(C4[2*gg][2]));
                float h03 = __bfloat162float(__float2bfloat16_rn(C4[2*gg][3]));
                float h10 = __bfloat162float(__float2bfloat16_rn(C4[2*gg+1][0]));
                float h11 = __bfloat162float(__float2bfloat16_rn(C4[2*gg+1][1]));
                float h12 = __bfloat162float(__float2bfloat16_rn(C4[2*gg+1][2]));
                float h13 = __bfloat162float(__float2bfloat16_rn(C4[2*gg+1][3]));
                pah[g][0] = pack2(C4[2*gg][0],   C4[2*gg][1]);
                pah[g][1] = pack2(C4[2*gg][2],   C4[2*gg][3]);
                pah[g][2] = pack2(C4[2*gg+1][0], C4[2*gg+1][1]);
                pah[g][3] = pack2(C4[2*gg+1][2], C4[2*gg+1][3]);
                pal[g][0] = pack2(C4[2*gg][0]-h00,   C4[2*gg][1]-h01);
                pal[g][1] = pack2(C4[2*gg][2]-h02,   C4[2*gg][3]-h03);
                pal[g][2] = pack2(C4[2*gg+1][0]-h10, C4[2*gg+1][1]-h11);
                pal[g][3] = pack2(C4[2*gg+1][2]-h12, C4[2*gg+1][3]-h13);
            }
        }

        __syncthreads();   // V stores visible; all score reads of A complete

        const bool more = (kc + 64 < SEQ);
        if (more)
            load_pair_regs(kreg, Kh, Kl, kc + 64, tid);

        pv_mma_half(vacc, pah, pal, Bsh, Bsl, lane, 0);
        pv_mma_half(vacc, pah, pal, Bsh, Bsl, lane, 1);

        if (more)
            store_pair_smem(kreg, Ash, Asl, tid);    // K(kc+64) -> A (score fenced)

        __syncthreads();   // K stores visible; all PV reads of B complete
    }

    lsum0 += __shfl_xor_sync(0xffffffffu, lsum0, 1);
    lsum0 += __shfl_xor_sync(0xffffffffu, lsum0, 2);
    lsum1 += __shfl_xor_sync(0xffffffffu, lsum1, 1);
    lsum1 += __shfl_xor_sync(0xffffffffu, lsum1, 2);
    const float invl0 = 1.0f / lsum0;
    const float invl1 = 1.0f / lsum1;

    if ((lane & 3) == 0) {
        g_invl[h * SEQ + q0 + w * 16 + r0]     = invl0;
        g_invl[h * SEQ + q0 + w * 16 + r0 + 8] = invl1;
    }

    {
        int rowg0 = q0 + w * 16 + r0;
        #pragma unroll
        for (int t = 0; t < 8; t++) {
            int col = h * DH + t * 8 + c0;
            *(float2*)&g_vals[(size_t)rowg0 * DM + col] =
                make_float2(vacc[t][0] * invl0, vacc[t][1] * invl0);
            *(float2*)&g_vals[(size_t)(rowg0 + 8) * DM + col] =
                make_float2(vacc[t][2] * invl1, vacc[t][3] * invl1);
        }
    }
}

// ---------------------------------------------------------------------------
// Normalize attn rows in place (bandwidth-bound, at roofline)
// ---------------------------------------------------------------------------
__global__ __launch_bounds__(256) void norm_kernel(float* __restrict__ attn)
{
    const int row = blockIdx.x;
    const float inv = g_invl[row];
    float4* p = (float4*)(attn + (size_t)row * SEQ);
    #pragma unroll
    for (int it = 0; it < 4; it++) {
        int i = threadIdx.x + it * 256;
        float4 v = p[i];
        v.x *= inv; v.y *= inv; v.z *= inv; v.w *= inv;
        p[i] = v;
    }
}

extern "C" void kernel_launch(void* const* d_in, const int* in_sizes, int n_in,
                              void* d_out, int out_size)
{
    const float* q  = (const float*)d_in[0];
    const float* k  = (const float*)d_in[1];
    const float* v  = (const float*)d_in[2];
    const float* Wq = (const float*)d_in[3];
    const float* bq = (const float*)d_in[4];
    const float* Wk = (const float*)d_in[5];
    const float* bk = (const float*)d_in[6];
    const float* Wv = (const float*)d_in[7];
    const float* bv = (const float*)d_in[8];
    const float* Wo = (const float*)d_in[9];
    const float* bo = (const float*)d_in[10];

    float* out  = (float*)d_out;
    float* attn = out + (size_t)SEQ * DM;

    dim3 g1(DM / 64, SEQ / 128, 3);
    proj_kernel<<<g1, 256>>>(q, k, v, Wq, bq, Wk, bk, Wv, bv);

    dim3 g2(SEQ / 64, NH);
    attn_kernel<<<g2, 128>>>(attn);

    dim3 g3(DM / 64, SEQ / 128);
    out_kernel<<<g3, 256>>>(out, Wo, bo);

    norm_kernel<<<NH * SEQ, 256>>>(attn);
}

// round 17
// speedup vs baseline: 1.3605x; 1.3605x over previous
#include <cuda_runtime.h>
#include <cuda_bf16.h>
#include <cstdint>
#include <cstddef>

#define SEQ 4096
#define DM  1024
#define NH  16
#define DH  64

// Scratch: Q/K/V stored as bf16 hi/lo split, head-major [h][s][d]
__device__ __align__(16) __nv_bfloat16 g_Qbh[NH * SEQ * DH];
__device__ __align__(16) __nv_bfloat16 g_Qbl[NH * SEQ * DH];
__device__ __align__(16) __nv_bfloat16 g_Kbh[NH * SEQ * DH];
__device__ __align__(16) __nv_bfloat16 g_Kbl[NH * SEQ * DH];
__device__ __align__(16) __nv_bfloat16 g_Vbh[NH * SEQ * DH];
__device__ __align__(16) __nv_bfloat16 g_Vbl[NH * SEQ * DH];
__device__ float g_vals[SEQ * DM];      // [s][h*64+d]
__device__ float g_invl[NH * SEQ];      // per-row 1/sumexp

// ---------------------------------------------------------------------------
// Helpers
// ---------------------------------------------------------------------------
__device__ __forceinline__ uint32_t s2u(const void* p) {
    return (uint32_t)__cvta_generic_to_shared(p);
}

__device__ __forceinline__ void ldsm_x4(uint32_t* r, uint32_t a) {
    asm volatile("ldmatrix.sync.aligned.m8n8.x4.shared.b16 {%0,%1,%2,%3}, [%4];"
                 : "=r"(r[0]), "=r"(r[1]), "=r"(r[2]), "=r"(r[3]) : "r"(a));
}

__device__ __forceinline__ void ldsm_x4t(uint32_t* r, uint32_t a) {
    asm volatile("ldmatrix.sync.aligned.m8n8.x4.trans.shared.b16 {%0,%1,%2,%3}, [%4];"
                 : "=r"(r[0]), "=r"(r[1]), "=r"(r[2]), "=r"(r[3]) : "r"(a));
}

__device__ __forceinline__ void mma_bf16(float* c, const uint32_t* a, uint32_t b0, uint32_t b1) {
    asm volatile("mma.sync.aligned.m16n8k16.row.col.f32.bf16.bf16.f32 "
                 "{%0,%1,%2,%3}, {%4,%5,%6,%7}, {%8,%9}, {%0,%1,%2,%3};"
                 : "+f"(c[0]), "+f"(c[1]), "+f"(c[2]), "+f"(c[3])
                 : "r"(a[0]), "r"(a[1]), "r"(a[2]), "r"(a[3]), "r"(b0), "r"(b1));
}

__device__ __forceinline__ uint32_t pack2(float a, float b) {
    __nv_bfloat162 t = __floats2bfloat162_rn(a, b);
    return *(uint32_t*)&t;
}

// streaming (evict-first) float2 store
__device__ __forceinline__ void stcs_f2(float* p, float a, float b) {
    asm volatile("st.global.cs.v2.f32 [%0], {%1, %2};" :: "l"(p), "f"(a), "f"(b) : "memory");
}

// Score MMA: C[8][4] += Q(16x64) @ K^T, 3-term split
__device__ __forceinline__ void score_mma(float C[8][4],
                                          const uint32_t qh[4][4], const uint32_t ql[4][4],
                                          const __nv_bfloat16* Bh, const __nv_bfloat16* Bl,
                                          int lane) {
    const int grp = lane >> 3;
    const int i   = lane & 7;
    #pragma unroll
    for (int t2 = 0; t2 < 4; t2++) {
        int nrow = t2 * 16 + (grp >> 1) * 8 + i;
        int ncol = (grp & 1) * 8;
        #pragma unroll
        for (int g = 0; g < 4; g++) {
            uint32_t kh[4], kl[4];
            ldsm_x4(kh, s2u(Bh + nrow * 72 + g * 16 + ncol));
            ldsm_x4(kl, s2u(Bl + nrow * 72 + g * 16 + ncol));
            mma_bf16(C[2 * t2],     qh[g], kh[0], kh[1]);
            mma_bf16(C[2 * t2],     ql[g], kh[0], kh[1]);
            mma_bf16(C[2 * t2],     qh[g], kl[0], kl[1]);
            mma_bf16(C[2 * t2 + 1], qh[g], kh[2], kh[3]);
            mma_bf16(C[2 * t2 + 1], ql[g], kh[2], kh[3]);
            mma_bf16(C[2 * t2 + 1], qh[g], kl[2], kl[3]);
        }
    }
}

// Row-major-B MMA: vacc[8][4] += A(16x64) @ B(64x64), B stored [k][n]
__device__ __forceinline__ void rowB_mma(float V[8][4],
                                         const uint32_t pah[4][4], const uint32_t pal[4][4],
                                         const __nv_bfloat16* Bh, const __nv_bfloat16* Bl,
                                         int lane) {
    const int grp = lane >> 3;
    const int i   = lane & 7;
    #pragma unroll
    for (int t2 = 0; t2 < 4; t2++) {
        int vcol = t2 * 16 + (grp >> 1) * 8;
        #pragma unroll
        for (int g = 0; g < 4; g++) {
            int vrow = g * 16 + (grp & 1) * 8 + i;
            uint32_t vh[4], vl[4];
            ldsm_x4t(vh, s2u(Bh + vrow * 72 + vcol));
            ldsm_x4t(vl, s2u(Bl + vrow * 72 + vcol));
            mma_bf16(V[2 * t2],     pah[g], vh[0], vh[1]);
            mma_bf16(V[2 * t2],     pal[g], vh[0], vh[1]);
            mma_bf16(V[2 * t2],     pah[g], vl[0], vl[1]);
            mma_bf16(V[2 * t2 + 1], pah[g], vh[2], vh[3]);
            mma_bf16(V[2 * t2 + 1], pal[g], vh[2], vh[3]);
            mma_bf16(V[2 * t2 + 1], pah[g], vl[2], vl[3]);
        }
    }
}

// ---------------------------------------------------------------------------
// GEMM core (tensor pipe, 2x2 warp tiling, register-staged prefetch):
// tile(64x64 @ m0,n0) = X @ W + b.  (R13 version, measured good.)
// ---------------------------------------------------------------------------
__device__ __forceinline__ void gc_load_regs(float4* xr, float4* wr,
                                             const float* __restrict__ Xp,
                                             const float* __restrict__ Wp,
                                             int k0, int tid) {
    #pragma unroll
    for (int it = 0; it < 8; it++) {
        int lin = tid + it * 128;
        int row = lin >> 4;
        int c4  = (lin & 15) << 2;
        xr[it] = *(const float4*)(Xp + (size_t)row * DM + k0 + c4);
        wr[it] = *(const float4*)(Wp + (size_t)(k0 + row) * DM + c4);
    }
}

__device__ __forceinline__ void gc_cvt_store(const float4* r,
                                             __nv_bfloat16* Bh, __nv_bfloat16* Bl,
                                             int tid) {
    #pragma unroll
    for (int it = 0; it < 8; it++) {
        int lin = tid + it * 128;
        int row = lin >> 4;
        int c4  = (lin & 15) << 2;
        float4 v = r[it];
        __nv_bfloat16 h0 = __float2bfloat16_rn(v.x);
        __nv_bfloat16 h1 = __float2bfloat16_rn(v.y);
        __nv_bfloat16 h2 = __float2bfloat16_rn(v.z);
        __nv_bfloat16 h3 = __float2bfloat16_rn(v.w);
        *(__nv_bfloat162*)(Bh + row * 72 + c4)     = __halves2bfloat162(h0, h1);
        *(__nv_bfloat162*)(Bh + row * 72 + c4 + 2) = __halves2bfloat162(h2, h3);
        *(__nv_bfloat162*)(Bl + row * 72 + c4) =
            __floats2bfloat162_rn(v.x - __bfloat162float(h0), v.y - __bfloat162float(h1));
        *(__nv_bfloat162*)(Bl + row * 72 + c4 + 2) =
            __floats2bfloat162_rn(v.z - __bfloat162float(h2), v.w - __bfloat162float(h3));
    }
}

__device__ __forceinline__ void gemm_core(const float* __restrict__ X,
                                          const float* __restrict__ W,
                                          const float* __restrict__ bias,
                                          float* __restrict__ dstf,
                                          __nv_bfloat16* __restrict__ dsth,
                                          __nv_bfloat16* __restrict__ dstl,
                                          float scale, int m0, int n0) {
    __shared__ __nv_bfloat16 Xsh[64 * 72];
    __shared__ __nv_bfloat16 Xsl[64 * 72];
    __shared__ __nv_bfloat16 Wsh[64 * 72];
    __shared__ __nv_bfloat16 Wsl[64 * 72];

    const int tid  = threadIdx.x;
    const int lane = tid & 31;
    const int w    = tid >> 5;
    const int wm   = w & 1;
    const int wn   = w >> 1;
    const int grp  = lane >> 3;
    const int li   = lane & 7;

    const float* Xp = X + (size_t)m0 * DM;
    const float* Wp = W + n0;

    float vacc[8][4];
    #pragma unroll
    for (int t = 0; t < 8; t++) {
        #pragma unroll
        for (int j = 0; j < 4; j++) vacc[t][j] = 0.f;
    }

    float4 xr[8], wr[8];
    gc_load_regs(xr, wr, Xp, Wp, 0, tid);

    for (int k0 = 0; k0 < DM; k0 += 64) {
        gc_cvt_store(xr, Xsh, Xsl, tid);
        gc_cvt_store(wr, Wsh, Wsl, tid);
        __syncthreads();

        if (k0 + 64 < DM)
            gc_load_regs(xr, wr, Xp, Wp, k0 + 64, tid);  // hidden under MMA

        #pragma unroll
        for (int kg = 0; kg < 4; kg++) {
            uint32_t ah[2][4], al[2][4];
            #pragma unroll
            for (int mh = 0; mh < 2; mh++) {
                int arow = wm * 32 + mh * 16 + (grp & 1) * 8 + li;
                int acol = kg * 16 + (grp >> 1) * 8;
                ldsm_x4(ah[mh], s2u(Xsh + arow * 72 + acol));
                ldsm_x4(al[mh], s2u(Xsl + arow * 72 + acol));
            }
            #pragma unroll
            for (int t = 0; t < 2; t++) {
                int vrow = kg * 16 + (grp & 1) * 8 + li;
                int vcol = wn * 32 + t * 16 + (grp >> 1) * 8;
                uint32_t vh[4], vl[4];
                ldsm_x4t(vh, s2u(Wsh + vrow * 72 + vcol));
                ldsm_x4t(vl, s2u(Wsl + vrow * 72 + vcol));
                #pragma unroll
                for (int mh = 0; mh < 2; mh++) {
                    float* c0p = vacc[mh * 4 + t * 2];
                    float* c1p = vacc[mh * 4 + t * 2 + 1];
                    mma_bf16(c0p, ah[mh], vh[0], vh[1]);
                    mma_bf16(c0p, al[mh], vh[0], vh[1]);
                    mma_bf16(c0p, ah[mh], vl[0], vl[1]);
                    mma_bf16(c1p, ah[mh], vh[2], vh[3]);
                    mma_bf16(c1p, al[mh], vh[2], vh[3]);
                    mma_bf16(c1p, ah[mh], vl[2], vl[3]);
                }
            }
        }
        __syncthreads();
    }

    const int r0 = lane >> 2;
    const int c0 = (lane & 3) * 2;
    #pragma unroll
    for (int u = 0; u < 8; u++) {
        int mh = u >> 2, q = u & 3;
        int row0 = m0 + wm * 32 + mh * 16 + r0;
        int coff = wn * 32 + q * 8 + c0;
        int col  = n0 + coff;
        float b0 = bias[col], b1 = bias[col + 1];
        float v00 = (vacc[u][0] + b0) * scale;
        float v01 = (vacc[u][1] + b1) * scale;
        float v10 = (vacc[u][2] + b0) * scale;
        float v11 = (vacc[u][3] + b1) * scale;
        if (dsth) {
            int hh = n0 >> 6;
            size_t base0 = ((size_t)hh * SEQ + row0) * DH + coff;
            size_t base1 = ((size_t)hh * SEQ + row0 + 8) * DH + coff;
            __nv_bfloat16 h00 = __float2bfloat16_rn(v00);
            __nv_bfloat16 h01 = __float2bfloat16_rn(v01);
            __nv_bfloat16 h10 = __float2bfloat16_rn(v10);
            __nv_bfloat16 h11 = __float2bfloat16_rn(v11);
            *(__nv_bfloat162*)&dsth[base0] = __halves2bfloat162(h00, h01);
            *(__nv_bfloat162*)&dsth[base1] = __halves2bfloat162(h10, h11);
            *(__nv_bfloat162*)&dstl[base0] =
                __floats2bfloat162_rn(v00 - __bfloat162float(h00), v01 - __bfloat162float(h01));
            *(__nv_bfloat162*)&dstl[base1] =
                __floats2bfloat162_rn(v10 - __bfloat162float(h10), v11 - __bfloat162float(h11));
        } else {
            *(float2*)&dstf[(size_t)row0 * DM + col]       = make_float2(v00, v01);
            *(float2*)&dstf[(size_t)(row0 + 8) * DM + col] = make_float2(v10, v11);
        }
    }
}

__global__ __launch_bounds__(128) void proj_kernel(
    const float* __restrict__ xq, const float* __restrict__ xk, const float* __restrict__ xv,
    const float* __restrict__ Wq, const float* __restrict__ bq,
    const float* __restrict__ Wk, const float* __restrict__ bk,
    const float* __restrict__ Wv, const float* __restrict__ bv)
{
    const float* X; const float* W; const float* b;
    __nv_bfloat16 *dh, *dl; float scale;
    // Q scale folds softmax 1/8 AND log2(e) so attn can use exp2f directly.
    if (blockIdx.z == 0)      { X = xq; W = Wq; b = bq; dh = g_Qbh; dl = g_Qbl; scale = 0.125f * 1.4426950408889634f; }
    else if (blockIdx.z == 1) { X = xk; W = Wk; b = bk; dh = g_Kbh; dl = g_Kbl; scale = 1.0f; }
    else                      { X = xv; W = Wv; b = bv; dh = g_Vbh; dl = g_Vbl; scale = 1.0f; }
    gemm_core(X, W, b, nullptr, dh, dl, scale, blockIdx.y * 64, blockIdx.x * 64);
}

__global__ __launch_bounds__(128) void out_kernel(
    float* __restrict__ out, const float* __restrict__ W, const float* __restrict__ b)
{
    gemm_core(g_vals, W, b, out, nullptr, nullptr, 1.0f, blockIdx.y * 64, blockIdx.x * 64);
}

// ---------------------------------------------------------------------------
// Attention: 64-query tiles, 128 threads, 2 buffer-pairs (Q pair reused as A),
// register-staged prefetch, TWO syncs per chunk.  (R11/R13 structure.)
// Attn writes use streaming stores (.cs) to keep K/V L2-resident.
// ---------------------------------------------------------------------------
__device__ __forceinline__ void load_pair_regs(uint4* r,
                                               const __nv_bfloat16* __restrict__ Ph,
                                               const __nv_bfloat16* __restrict__ Pl,
                                               int kc, int tid) {
    #pragma unroll
    for (int it = 0; it < 4; it++) {
        int lin = tid + it * 128;
        int row = lin >> 3;
        int c8  = (lin & 7) * 8;
        r[it]     = *(const uint4*)(Ph + (size_t)(kc + row) * DH + c8);
        r[4 + it] = *(const uint4*)(Pl + (size_t)(kc + row) * DH + c8);
    }
}

__device__ __forceinline__ void store_pair_smem(const uint4* r,
                                                __nv_bfloat16* Bh, __nv_bfloat16* Bl,
                                                int tid) {
    #pragma unroll
    for (int it = 0; it < 4; it++) {
        int lin = tid + it * 128;
        int row = lin >> 3;
        int c8  = (lin & 7) * 8;
        *(uint4*)(Bh + row * 72 + c8) = r[it];
        *(uint4*)(Bl + row * 72 + c8) = r[4 + it];
    }
}

__global__ __launch_bounds__(128) void attn_kernel(float* __restrict__ attn_out)
{
    __shared__ __nv_bfloat16 Ash[64 * 72];   // Q staging, then K buffer
    __shared__ __nv_bfloat16 Asl[64 * 72];
    __shared__ __nv_bfloat16 Bsh[64 * 72];   // V buffer
    __shared__ __nv_bfloat16 Bsl[64 * 72];

    const int h    = blockIdx.y;
    const int q0   = blockIdx.x * 64;
    const int tid  = threadIdx.x;
    const int lane = tid & 31;
    const int w    = tid >> 5;

    const __nv_bfloat16* Qh = g_Qbh + ((size_t)h * SEQ + q0) * DH;
    const __nv_bfloat16* Ql = g_Qbl + ((size_t)h * SEQ + q0) * DH;
    const __nv_bfloat16* Kh = g_Kbh + (size_t)h * SEQ * DH;
    const __nv_bfloat16* Kl = g_Kbl + (size_t)h * SEQ * DH;
    const __nv_bfloat16* Vh = g_Vbh + (size_t)h * SEQ * DH;
    const __nv_bfloat16* Vl = g_Vbl + (size_t)h * SEQ * DH;

    // Q -> A buffers
    #pragma unroll
    for (int it = 0; it < 4; it++) {
        int lin = tid + it * 128;
        int row = lin >> 3;
        int c8  = (lin & 7) * 8;
        *(uint4*)&Ash[row * 72 + c8] = *(const uint4*)&Qh[(size_t)row * DH + c8];
        *(uint4*)&Asl[row * 72 + c8] = *(const uint4*)&Ql[(size_t)row * DH + c8];
    }

    // prefetch K chunk 0 into registers (overlaps Q fragment extraction)
    uint4 kreg[8], vreg[8];
    load_pair_regs(kreg, Kh, Kl, 0, tid);

    __syncthreads();

    // Q fragments (resident all kernel)
    uint32_t qfh[4][4], qfl[4][4];
    {
        int grp = lane >> 3, i = lane & 7;
        int qrow = w * 16 + (grp & 1) * 8 + i;
        #pragma unroll
        for (int g = 0; g < 4; g++) {
            int qcol = g * 16 + (grp >> 1) * 8;
            ldsm_x4(qfh[g], s2u(Ash + qrow * 72 + qcol));
            ldsm_x4(qfl[g], s2u(Asl + qrow * 72 + qcol));
        }
    }
    __syncthreads();                 // all warps done reading Q from A

    store_pair_smem(kreg, Ash, Asl, tid);   // K0 -> A
    __syncthreads();

    float vacc[8][4];
    #pragma unroll
    for (int t = 0; t < 8; t++) {
        #pragma unroll
        for (int j = 0; j < 4; j++) vacc[t][j] = 0.f;
    }
    float lsum0 = 0.f, lsum1 = 0.f;

    const int r0 = lane >> 2;
    const int c0 = (lane & 3) * 2;
    float* arow0 = attn_out + ((size_t)h * SEQ + q0 + w * 16 + r0) * SEQ;
    float* arow1 = arow0 + (size_t)8 * SEQ;

    for (int kc = 0; kc < SEQ; kc += 64) {
        // issue V(kc) loads; latency hidden under score MMA
        load_pair_regs(vreg, Vh, Vl, kc, tid);

        float C[8][4];
        #pragma unroll
        for (int t = 0; t < 8; t++) {
            #pragma unroll
            for (int j = 0; j < 4; j++) C[t][j] = 0.f;
        }
        score_mma(C, qfh, qfl, Ash, Asl, lane);      // read A = K(kc)

        store_pair_smem(vreg, Bsh, Bsl, tid);        // V(kc) -> B (prev PV fenced)

        // exp2 (Q pre-scaled by log2e), streaming-write unnormalized attn
        uint32_t pah[4][4], pal[4][4];
        #pragma unroll
        for (int t = 0; t < 8; t++) {
            float p0 = exp2f(C[t][0]);
            float p1 = exp2f(C[t][1]);
            float p2 = exp2f(C[t][2]);
            float p3 = exp2f(C[t][3]);
            stcs_f2(arow0 + kc + t * 8 + c0, p0, p1);
            stcs_f2(arow1 + kc + t * 8 + c0, p2, p3);
            lsum0 += p0 + p1;
            lsum1 += p2 + p3;
            C[t][0] = p0; C[t][1] = p1; C[t][2] = p2; C[t][3] = p3;
        }
        #pragma unroll
        for (int g = 0; g < 4; g++) {
            float h00 = __bfloat162float(__float2bfloat16_rn(C[2*g][0]));
            float h01 = __bfloat162float(__float2bfloat16_rn(C[2*g][1]));
            float h02 = __bfloat162float(__float2bfloat16_rn(C[2*g][2]));
            float h03 = __bfloat162float(__float2bfloat16_rn(C[2*g][3]));
            float h10 = __bfloat162float(__float2bfloat16_rn(C[2*g+1][0]));
            float h11 = __bfloat162float(__float2bfloat16_rn(C[2*g+1][1]));
            float h12 = __bfloat162float(__float2bfloat16_rn(C[2*g+1][2]));
            float h13 = __bfloat162float(__float2bfloat16_rn(C[2*g+1][3]));
            pah[g][0] = pack2(C[2*g][0],   C[2*g][1]);
            pah[g][1] = pack2(C[2*g][2],   C[2*g][3]);
            pah[g][2] = pack2(C[2*g+1][0], C[2*g+1][1]);
            pah[g][3] = pack2(C[2*g+1][2], C[2*g+1][3]);
            pal[g][0] = pack2(C[2*g][0]-h00,   C[2*g][1]-h01);
            pal[g][1] = pack2(C[2*g][2]-h02,   C[2*g][3]-h03);
            pal[g][2] = pack2(C[2*g+1][0]-h10, C[2*g+1][1]-h11);
            pal[g][3] = pack2(C[2*g+1][2]-h12, C[2*g+1][3]-h13);
        }

        __syncthreads();   // V stores visible; all score reads of A complete

        // issue K(kc+64) loads; latency hidden under PV MMA
        const bool more = (kc + 64 < SEQ);
        if (more)
            load_pair_regs(kreg, Kh, Kl, kc + 64, tid);

        rowB_mma(vacc, pah, pal, Bsh, Bsl, lane);    // read B = V(kc)

        if (more)
            store_pair_smem(kreg, Ash, Asl, tid);    // K(kc+64) -> A (score fenced)

        __syncthreads();   // K stores visible; all PV reads of B complete
    }

    lsum0 += __shfl_xor_sync(0xffffffffu, lsum0, 1);
    lsum0 += __shfl_xor_sync(0xffffffffu, lsum0, 2);
    lsum1 += __shfl_xor_sync(0xffffffffu, lsum1, 1);
    lsum1 += __shfl_xor_sync(0xffffffffu, lsum1, 2);
    const float invl0 = 1.0f / lsum0;
    const float invl1 = 1.0f / lsum1;

    if ((lane & 3) == 0) {
        g_invl[h * SEQ + q0 + w * 16 + r0]     = invl0;
        g_invl[h * SEQ + q0 + w * 16 + r0 + 8] = invl1;
    }

    {
        int rowg0 = q0 + w * 16 + r0;
        #pragma unroll
        for (int t = 0; t < 8; t++) {
            int col = h * DH + t * 8 + c0;
            *(float2*)&g_vals[(size_t)rowg0 * DM + col] =
                make_float2(vacc[t][0] * invl0, vacc[t][1] * invl0);
            *(float2*)&g_vals[(size_t)(rowg0 + 8) * DM + col] =
                make_float2(vacc[t][2] * invl1, vacc[t][3] * invl1);
        }
    }
}

// ---------------------------------------------------------------------------
// Normalize attn rows in place (bandwidth-bound, at roofline)
// ---------------------------------------------------------------------------
__global__ __launch_bounds__(256) void norm_kernel(float* __restrict__ attn)
{
    const int row = blockIdx.x;
    const float inv = g_invl[row];
    float4* p = (float4*)(attn + (size_t)row * SEQ);
    #pragma unroll
    for (int it = 0; it < 4; it++) {
        int i = threadIdx.x + it * 256;
        float4 v = p[i];
        v.x *= inv; v.y *= inv; v.z *= inv; v.w *= inv;
        p[i] = v;
    }
}

extern "C" void kernel_launch(void* const* d_in, const int* in_sizes, int n_in,
                              void* d_out, int out_size)
{
    const float* q  = (const float*)d_in[0];
    const float* k  = (const float*)d_in[1];
    const float* v  = (const float*)d_in[2];
    const float* Wq = (const float*)d_in[3];
    const float* bq = (const float*)d_in[4];
    const float* Wk = (const float*)d_in[5];
    const float* bk = (const float*)d_in[6];
    const float* Wv = (const float*)d_in[7];
    const float* bv = (const float*)d_in[8];
    const float* Wo = (const float*)d_in[9];
    const float* bo = (const float*)d_in[10];

    float* out  = (float*)d_out;
    float* attn = out + (size_t)SEQ * DM;

    dim3 g1(DM / 64, SEQ / 64, 3);
    proj_kernel<<<g1, 128>>>(q, k, v, Wq, bq, Wk, bk, Wv, bv);

    dim3 g2(SEQ / 64, NH);
    attn_kernel<<<g2, 128>>>(attn);

    dim3 g3(DM / 64, SEQ / 64);
    out_kernel<<<g3, 128>>>(out, Wo, bo);

    norm_kernel<<<NH * SEQ, 256>>>(attn);
}